// round 16
// baseline (speedup 1.0000x reference)
#include <cuda_runtime.h>
#include <cfloat>
#include <cstdint>

#define BB 8
#define CC 64
#define NN 4096
#define OO 64
#define KNB 20
#define FULLMASK 0xffffffffu
#define MAXCH 28

// Scratch (device globals: allocation-free per harness rules)
__device__ float g_pd[134217728];   // [B*N, N] pairwise "distance", 537MB
__device__ float g_cmax[4194304];   // [B*N, 128] per-32-col-chunk max, 16MB
__device__ float g_sq[32768];       // [B*N] squared norms
__device__ float g_P[2097152];      // [B*N, O]  x·(W1-W2)^T
__device__ float g_Q[2097152];      // [B*N, O]  x·W2^T

// packed f32x2 FMA: d = a*b + d, elementwise on two fp32 lanes (IEEE .rn each)
__device__ __forceinline__ void ffma2(unsigned long long& d,
                                      unsigned long long a,
                                      unsigned long long b) {
    asm("fma.rn.f32x2 %0, %1, %2, %0;" : "+l"(d) : "l"(a), "l"(b));
}
__device__ __forceinline__ unsigned long long dup2(float v) {
    unsigned long long r;
    asm("mov.b64 %0, {%1, %1};" : "=l"(r) : "r"(__float_as_uint(v)));
    return r;
}

// ---------------------------------------------------------------------------
// Kernel 1: squared norms. sq[b,n] = sum_c x[b,c,n]^2 (same FMA order as GEMM)
// ---------------------------------------------------------------------------
__global__ void sq_kernel(const float* __restrict__ x) {
    int t = blockIdx.x * blockDim.x + threadIdx.x;   // 0..32767
    int b = t >> 12, n = t & 4095;
    const float* xp = x + (size_t)b * CC * NN + n;
    float s = 0.f;
    #pragma unroll
    for (int c = 0; c < CC; ++c) {
        float v = xp[(size_t)c * NN];
        s = fmaf(v, v, s);
    }
    g_sq[t] = s;
}

// ---------------------------------------------------------------------------
// Kernel 2: P = x·(W1-W2)^T, Q = x·W2^T   (collapses the edge GEMM)
// ---------------------------------------------------------------------------
__global__ __launch_bounds__(256) void pq_kernel(const float* __restrict__ x,
                                                 const float* __restrict__ W) {
    __shared__ float Wa[CC][OO + 1];
    __shared__ float Wb[CC][OO + 1];
    __shared__ float xs[CC][4];
    int tid = threadIdx.x;
    #pragma unroll
    for (int i = 0; i < 16; ++i) {
        int fid = tid + i * 256;
        int o = fid >> 6, c = fid & 63;
        float w1 = W[o * 128 + c];
        float w2 = W[o * 128 + 64 + c];
        Wa[c][o] = w1 - w2;
        Wb[c][o] = w2;
    }
    int nbase = blockIdx.x * 4;
    int b = nbase >> 12;
    int nb = nbase & 4095;
    {
        int c = tid >> 2, j = tid & 3;
        xs[c][j] = x[(size_t)b * CC * NN + (size_t)c * NN + nb + j];
    }
    __syncthreads();
    int o = tid & 63, nl = tid >> 6;
    float p = 0.f, q = 0.f;
    #pragma unroll
    for (int c = 0; c < CC; ++c) {
        float xv = xs[c][nl];
        p = fmaf(xv, Wa[c][o], p);
        q = fmaf(xv, Wb[c][o], q);
    }
    size_t g = (size_t)(nbase + nl);
    g_P[g * OO + o] = p;
    g_Q[g * OO + o] = q;
}

// ---------------------------------------------------------------------------
// Kernel 3: symmetric pd GEMM (FFMA2 mainloop), triangular grid, single
// launch over all batches. Normal store coalesced from registers; mirror
// store staged through reused operand smem (swizzled) so it is coalesced too.
// Same FMA c-order as sq_kernel => diagonal exactly 0.   (R15, proven ~294us)
// ---------------------------------------------------------------------------
__global__ __launch_bounds__(256) void pd_gemm_sym(const float* __restrict__ x) {
    __shared__ __align__(16) char smem_all[68608];
    float* As  = (float*)smem_all;               // As[c][v] = As[c*128+v]
    float* Bs  = (float*)(smem_all + 32768);
    float* sqn = (float*)(smem_all + 67584);
    float* sqm = (float*)(smem_all + 68096);

    // linear tile id -> (nt <= mt), t = mt(mt+1)/2 + nt
    int t = blockIdx.x;
    int mt = (int)((sqrtf(8.f * (float)t + 1.f) - 1.f) * 0.5f);
    while ((mt + 1) * (mt + 2) / 2 <= t) ++mt;
    while (mt * (mt + 1) / 2 > t) --mt;
    int nt = t - mt * (mt + 1) / 2;

    int b = blockIdx.z;
    int n0 = nt * 128, m0 = mt * 128;
    const float* xb = x + (size_t)b * CC * NN;
    int tid = threadIdx.x;

    #pragma unroll
    for (int i = 0; i < 8; ++i) {
        int fid = tid + i * 256;
        int c = fid >> 5, v = (fid & 31) << 2;
        *(float4*)&As[c * 128 + v] = *(const float4*)&xb[(size_t)c * NN + n0 + v];
        *(float4*)&Bs[c * 128 + v] = *(const float4*)&xb[(size_t)c * NN + m0 + v];
    }
    if (tid < 128)       sqn[tid]       = g_sq[b * NN + n0 + tid];
    else                 sqm[tid - 128] = g_sq[b * NN + m0 + (tid - 128)];
    __syncthreads();

    int tx = tid & 15, ty = tid >> 4;

    unsigned long long acc2[8][4];
    #pragma unroll
    for (int i = 0; i < 8; ++i)
        #pragma unroll
        for (int jp = 0; jp < 4; ++jp) acc2[i][jp] = 0ull;

    #pragma unroll 4
    for (int c = 0; c < CC; ++c) {
        float ar[8];
        *(float4*)&ar[0] = *(float4*)&As[c * 128 + ty * 8];
        *(float4*)&ar[4] = *(float4*)&As[c * 128 + ty * 8 + 4];
        ulonglong2 bl = *(ulonglong2*)&Bs[c * 128 + tx * 8];
        ulonglong2 bh = *(ulonglong2*)&Bs[c * 128 + tx * 8 + 4];
        unsigned long long br2[4] = {bl.x, bl.y, bh.x, bh.y};
        #pragma unroll
        for (int i = 0; i < 8; ++i) {
            unsigned long long ad = dup2(ar[i]);
            #pragma unroll
            for (int jp = 0; jp < 4; ++jp)
                ffma2(acc2[i][jp], ad, br2[jp]);
        }
    }

    float acc[8][8];
    #pragma unroll
    for (int i = 0; i < 8; ++i)
        #pragma unroll
        for (int jp = 0; jp < 4; ++jp) {
            float2 f = *(float2*)&acc2[i][jp];
            acc[i][jp * 2]     = f.x;
            acc[i][jp * 2 + 1] = f.y;
        }

    // ---- normal store + n-side chunkmax (coalesced)
    float* outp = g_pd + ((size_t)(b * NN + n0)) * NN + m0;
    float* cmn  = g_cmax + ((size_t)(b * NN + n0)) * 128 + (m0 >> 5);
    #pragma unroll
    for (int i = 0; i < 8; ++i) {
        int r = ty * 8 + i;
        float sn = sqn[r];
        float res[8];
        #pragma unroll
        for (int j = 0; j < 8; ++j)
            res[j] = 2.f * acc[i][j] - sn - sqm[tx * 8 + j];
        *(float4*)&outp[(size_t)r * NN + tx * 8]     = *(float4*)&res[0];
        *(float4*)&outp[(size_t)r * NN + tx * 8 + 4] = *(float4*)&res[4];
        float rm = fmaxf(fmaxf(fmaxf(res[0], res[1]), fmaxf(res[2], res[3])),
                         fmaxf(fmaxf(res[4], res[5]), fmaxf(res[6], res[7])));
        rm = fmaxf(rm, __shfl_xor_sync(FULLMASK, rm, 1));
        rm = fmaxf(rm, __shfl_xor_sync(FULLMASK, rm, 2));
        if ((tx & 3) == 0)
            cmn[(size_t)r * 128 + (tx >> 2)] = rm;
    }

    // ---- mirror via swizzled smem stage, coalesced copy-out + chunkmax
    if (nt != mt) {
        __syncthreads();
        float* stage = (float*)smem_all;
        #pragma unroll
        for (int j = 0; j < 8; ++j) {
            int rm = tx * 8 + j;
            float smv = sqm[rm];
            float tmp[8];
            #pragma unroll
            for (int i = 0; i < 8; ++i)
                tmp[i] = 2.f * acc[i][j] - sqn[ty * 8 + i] - smv;
            int sw = (tx & 15) << 1;
            int s0 = (ty * 2)     ^ sw;
            int s1 = (ty * 2 + 1) ^ sw;
            *(float4*)&stage[rm * 132 + s0 * 4] = *(float4*)&tmp[0];
            *(float4*)&stage[rm * 132 + s1 * 4] = *(float4*)&tmp[4];
        }
        __syncthreads();
        int wid2 = tid >> 5, lane = tid & 31;
        #pragma unroll 4
        for (int it = 0; it < 16; ++it) {
            int mr = it * 8 + wid2;
            int ps = lane ^ (((mr >> 3) & 15) << 1);
            float4 f = *(float4*)&stage[mr * 132 + ps * 4];
            float mx = fmaxf(fmaxf(f.x, f.y), fmaxf(f.z, f.w));
            mx = fmaxf(mx, __shfl_xor_sync(FULLMASK, mx, 1));
            mx = fmaxf(mx, __shfl_xor_sync(FULLMASK, mx, 2));
            mx = fmaxf(mx, __shfl_xor_sync(FULLMASK, mx, 4));
            *(float4*)&g_pd[((size_t)(b * NN + m0 + mr)) * NN + n0 + lane * 4] = f;
            if ((lane & 7) == 0)
                g_cmax[(size_t)(b * NN + m0 + mr) * 128 + nt * 4 + (lane >> 3)] = mx;
        }
    }
}

// float -> descending-orderable key (ascending uint sort picks largest first)
__device__ __forceinline__ unsigned int fdesc_key(float v) {
    unsigned int u = __float_as_uint(v);
    u = u ^ (((int)u >> 31) | 0x80000000u);
    return ~u;
}

// ---------------------------------------------------------------------------
// Kernel 4: warp-per-row top-20. Two-phase collect:
//   A) build candidate-chunk list from cm regs (no loads), then prefetch all
//      chunks into smem with NO intervening ballots -> loads pipeline (MLP)
//   B) filter+compact from smem, 64-key bitonic sort (identical to R12)
// Fallback to proven global sequential scan on nc>MAXCH or cnt>64.
// ---------------------------------------------------------------------------
__global__ __launch_bounds__(256) void topk_fused(
    const float* __restrict__ gamma, const float* __restrict__ beta,
    const float* __restrict__ rmean, const float* __restrict__ rvar,
    float* __restrict__ out)
{
    __shared__ float vbuf[8][MAXCH][32];
    __shared__ unsigned long long keybuf[8][64];
    __shared__ unsigned char clist[8][128];
    int warp = threadIdx.x >> 5, lane = threadIdx.x & 31;
    int row = blockIdx.x * 8 + warp;        // 0..32767
    int b = row >> 12, n = row & 4095;

    const float* cmrow = g_cmax + (size_t)row * 128;
    float cm[4];
    #pragma unroll
    for (int j = 0; j < 4; ++j) cm[j] = __ldg(&cmrow[j * 32 + lane]);
    float lmax = fmaxf(fmaxf(cm[0], cm[1]), fmaxf(cm[2], cm[3]));

    // bitonic sort 32 lane-group maxes ascending across lanes
    float s = lmax;
    #pragma unroll
    for (int k2 = 2; k2 <= 32; k2 <<= 1) {
        #pragma unroll
        for (int j2 = k2 >> 1; j2 > 0; j2 >>= 1) {
            float o = __shfl_xor_sync(FULLMASK, s, j2);
            bool dirAsc = ((lane & k2) == 0);
            bool upper  = ((lane & j2) == 0);
            float mn = fminf(s, o), mx = fmaxf(s, o);
            s = (dirAsc == upper) ? mn : mx;
        }
    }
    float T0 = __shfl_sync(FULLMASK, s, 32 - KNB);   // 20th largest group max

    const float* rowf = g_pd + (size_t)row * NN;
    unsigned lanelt = (1u << lane) - 1u;

    // ---- build candidate chunk list (register-only ballots)
    int nc = 0;
    #pragma unroll
    for (int j = 0; j < 4; ++j) {
        unsigned m = __ballot_sync(FULLMASK, cm[j] >= T0);
        if (cm[j] >= T0) {
            int pos = nc + __popc(m & lanelt);
            if (pos < 128) clist[warp][pos] = (unsigned char)(j * 32 + lane);
        }
        nc += __popc(m);
    }
    __syncwarp();

    int li = 0;   // lanes 0..19 will hold the top-20 indices
    bool fast = (nc <= MAXCH);
    int cnt = 0;

    if (fast) {
        // ---- Phase A: prefetch all candidate chunks (independent loads)
        for (int i = 0; i < nc; ++i) {
            int ch = clist[warp][i];
            vbuf[warp][i][lane] = __ldg(&rowf[ch * 32 + lane]);
        }
        __syncwarp();
        // ---- Phase B: filter + compact from smem
        for (int i = 0; i < nc; ++i) {
            float v = vbuf[warp][i][lane];
            int chunk = clist[warp][i];
            unsigned m = __ballot_sync(FULLMASK, v >= T0);
            int pos = cnt + __popc(m & lanelt);
            if (v >= T0 && pos < 64) {
                unsigned long long key =
                    ((unsigned long long)fdesc_key(v) << 32)
                    | (unsigned int)(chunk * 32 + lane);
                keybuf[warp][pos] = key;
            }
            cnt += __popc(m);
        }
    }

    if (fast && cnt <= 64) {
        // ---- 64-element bitonic sort (2 keys/lane)
        const unsigned long long PADK = 0xFFFFFFFFFFFFFFFFull;
        unsigned long long e0 = (lane      < cnt) ? keybuf[warp][lane]      : PADK;
        unsigned long long e1 = (lane + 32 < cnt) ? keybuf[warp][lane + 32] : PADK;
        #pragma unroll
        for (int k2 = 2; k2 <= 64; k2 <<= 1) {
            #pragma unroll
            for (int j2 = k2 >> 1; j2 > 0; j2 >>= 1) {
                if (j2 == 32) {
                    unsigned long long lo = e0 < e1 ? e0 : e1;
                    unsigned long long hi = e0 < e1 ? e1 : e0;
                    e0 = lo; e1 = hi;
                } else {
                    bool up = ((lane & j2) == 0);
                    {
                        bool asc = ((lane & k2) == 0) || (k2 == 64);
                        unsigned long long o = __shfl_xor_sync(FULLMASK, e0, j2);
                        unsigned long long mn = e0 < o ? e0 : o;
                        unsigned long long mx = e0 < o ? o : e0;
                        e0 = (asc == up) ? mn : mx;
                    }
                    {
                        bool asc = (((lane + 32) & k2) == 0) || (k2 == 64);
                        unsigned long long o = __shfl_xor_sync(FULLMASK, e1, j2);
                        unsigned long long mn = e1 < o ? e1 : o;
                        unsigned long long mx = e1 < o ? o : e1;
                        e1 = (asc == up) ? mn : mx;
                    }
                }
            }
        }
        li = (int)(unsigned int)(e0 & 0xFFFFFFFFull);
    } else {
        // ---- fallback: exact sequential insert scan from global (proven)
        float lv = -FLT_MAX;
        float vmin = -FLT_MAX;
        int   minpos = 0;
        #pragma unroll
        for (int j = 0; j < 4; ++j) {
            unsigned cmask = __ballot_sync(FULLMASK, cm[j] >= T0);
            while (cmask) {
                int q = __ffs(cmask) - 1;
                cmask &= cmask - 1;
                float cmv = __shfl_sync(FULLMASK, cm[j], q);
                if (cmv <= vmin && vmin > -FLT_MAX) continue;
                int chunk = j * 32 + q;
                float v = __ldg(&rowf[chunk * 32 + lane]);
                unsigned m = __ballot_sync(FULLMASK, v >= T0 && v > vmin);
                while (m) {
                    int lead = __ffs(m) - 1;
                    float cv = __shfl_sync(FULLMASK, v, lead);
                    int   ci = chunk * 32 + lead;
                    if (lane == minpos) { lv = cv; li = ci; }
                    float tt = (lane < KNB) ? lv : FLT_MAX;
                    #pragma unroll
                    for (int off = 16; off; off >>= 1)
                        tt = fminf(tt, __shfl_xor_sync(FULLMASK, tt, off));
                    vmin = tt;
                    minpos = __ffs(__ballot_sync(FULLMASK,
                                                 lane < KNB && lv == vmin)) - 1;
                    m &= ~(1u << lead);
                    m &= __ballot_sync(FULLMASK, v > vmin);
                }
            }
        }
    }

    // ---- fused epilogue: out[b,o,n] = max_k leaky(BN(P[row,o] + Q[idx_k,o]))
    float sc1 = gamma[lane]      * rsqrtf(rvar[lane]      + 1e-5f);
    float sc2 = gamma[lane + 32] * rsqrtf(rvar[lane + 32] + 1e-5f);
    float bi1 = beta[lane]      - rmean[lane]      * sc1;
    float bi2 = beta[lane + 32] - rmean[lane + 32] * sc2;
    float p1 = g_P[(size_t)row * OO + lane];
    float p2 = g_P[(size_t)row * OO + lane + 32];
    const float* Qb = g_Q + (size_t)b * NN * OO;

    float m1 = -FLT_MAX, m2 = -FLT_MAX;
    #pragma unroll
    for (int kk = 0; kk < KNB; ++kk) {
        int nid = __shfl_sync(FULLMASK, li, kk);
        const float* Qr = Qb + (size_t)nid * OO;
        float y1 = (p1 + __ldg(&Qr[lane]))      * sc1 + bi1;
        float y2 = (p2 + __ldg(&Qr[lane + 32])) * sc2 + bi2;
        y1 = (y1 >= 0.f) ? y1 : 0.2f * y1;
        y2 = (y2 >= 0.f) ? y2 : 0.2f * y2;
        m1 = fmaxf(m1, y1);
        m2 = fmaxf(m2, y2);
    }
    out[((size_t)b * OO + lane)      * NN + n] = m1;
    out[((size_t)b * OO + lane + 32) * NN + n] = m2;
}

// ---------------------------------------------------------------------------
extern "C" void kernel_launch(void* const* d_in, const int* in_sizes, int n_in,
                              void* d_out, int out_size) {
    const float* x     = (const float*)d_in[0];
    const float* W     = (const float*)d_in[1];
    const float* gamma = (const float*)d_in[2];
    const float* beta  = (const float*)d_in[3];
    const float* rmean = (const float*)d_in[4];
    const float* rvar  = (const float*)d_in[5];
    float* out = (float*)d_out;

    sq_kernel<<<128, 256>>>(x);
    pq_kernel<<<8192, 256>>>(x, W);
    {
        dim3 grid(528, 1, BB);
        pd_gemm_sym<<<grid, 256>>>(x);
    }
    topk_fused<<<4096, 256>>>(gamma, beta, rmean, rvar, out);
}

// round 17
// speedup vs baseline: 1.1895x; 1.1895x over previous
#include <cuda_runtime.h>
#include <cfloat>
#include <cstdint>

#define BB 8
#define CC 64
#define NN 4096
#define OO 64
#define KNB 20
#define FULLMASK 0xffffffffu

// Scratch (device globals: allocation-free per harness rules)
__device__ float g_pd[134217728];   // [B*N, N] pairwise "distance", 537MB
__device__ float g_cmax[4194304];   // [B*N, 128] per-32-col-chunk max, 16MB
__device__ float g_sq[32768];       // [B*N] squared norms
__device__ float g_P[2097152];      // [B*N, O]  x·(W1-W2)^T
__device__ float g_Q[2097152];      // [B*N, O]  x·W2^T

// packed f32x2 FMA: d = a*b + d, elementwise on two fp32 lanes (IEEE .rn each)
__device__ __forceinline__ void ffma2(unsigned long long& d,
                                      unsigned long long a,
                                      unsigned long long b) {
    asm("fma.rn.f32x2 %0, %1, %2, %0;" : "+l"(d) : "l"(a), "l"(b));
}
__device__ __forceinline__ unsigned long long dup2(float v) {
    unsigned long long r;
    asm("mov.b64 %0, {%1, %1};" : "=l"(r) : "r"(__float_as_uint(v)));
    return r;
}

// ---------------------------------------------------------------------------
// Kernel 1: squared norms. sq[b,n] = sum_c x[b,c,n]^2 (same FMA order as GEMM)
// ---------------------------------------------------------------------------
__global__ void sq_kernel(const float* __restrict__ x) {
    int t = blockIdx.x * blockDim.x + threadIdx.x;   // 0..32767
    int b = t >> 12, n = t & 4095;
    const float* xp = x + (size_t)b * CC * NN + n;
    float s = 0.f;
    #pragma unroll
    for (int c = 0; c < CC; ++c) {
        float v = xp[(size_t)c * NN];
        s = fmaf(v, v, s);
    }
    g_sq[t] = s;
}

// ---------------------------------------------------------------------------
// Kernel 2: P = x·(W1-W2)^T, Q = x·W2^T   (collapses the edge GEMM)
// ---------------------------------------------------------------------------
__global__ __launch_bounds__(256) void pq_kernel(const float* __restrict__ x,
                                                 const float* __restrict__ W) {
    __shared__ float Wa[CC][OO + 1];
    __shared__ float Wb[CC][OO + 1];
    __shared__ float xs[CC][4];
    int tid = threadIdx.x;
    #pragma unroll
    for (int i = 0; i < 16; ++i) {
        int fid = tid + i * 256;
        int o = fid >> 6, c = fid & 63;
        float w1 = W[o * 128 + c];
        float w2 = W[o * 128 + 64 + c];
        Wa[c][o] = w1 - w2;
        Wb[c][o] = w2;
    }
    int nbase = blockIdx.x * 4;
    int b = nbase >> 12;
    int nb = nbase & 4095;
    {
        int c = tid >> 2, j = tid & 3;
        xs[c][j] = x[(size_t)b * CC * NN + (size_t)c * NN + nb + j];
    }
    __syncthreads();
    int o = tid & 63, nl = tid >> 6;
    float p = 0.f, q = 0.f;
    #pragma unroll
    for (int c = 0; c < CC; ++c) {
        float xv = xs[c][nl];
        p = fmaf(xv, Wa[c][o], p);
        q = fmaf(xv, Wb[c][o], q);
    }
    size_t g = (size_t)(nbase + nl);
    g_P[g * OO + o] = p;
    g_Q[g * OO + o] = q;
}

// ---------------------------------------------------------------------------
// Kernel 3: symmetric pd GEMM (FFMA2 mainloop), triangular grid, single
// launch over all batches. Normal store coalesced from registers; mirror
// store staged through reused operand smem (swizzled) so it is coalesced too.
// Same FMA c-order as sq_kernel => diagonal exactly 0.   (R15, proven ~294us)
// ---------------------------------------------------------------------------
__global__ __launch_bounds__(256) void pd_gemm_sym(const float* __restrict__ x) {
    __shared__ __align__(16) char smem_all[68608];
    float* As  = (float*)smem_all;               // As[c][v] = As[c*128+v]
    float* Bs  = (float*)(smem_all + 32768);
    float* sqn = (float*)(smem_all + 67584);
    float* sqm = (float*)(smem_all + 68096);

    // linear tile id -> (nt <= mt), t = mt(mt+1)/2 + nt
    int t = blockIdx.x;
    int mt = (int)((sqrtf(8.f * (float)t + 1.f) - 1.f) * 0.5f);
    while ((mt + 1) * (mt + 2) / 2 <= t) ++mt;
    while (mt * (mt + 1) / 2 > t) --mt;
    int nt = t - mt * (mt + 1) / 2;

    int b = blockIdx.z;
    int n0 = nt * 128, m0 = mt * 128;
    const float* xb = x + (size_t)b * CC * NN;
    int tid = threadIdx.x;

    #pragma unroll
    for (int i = 0; i < 8; ++i) {
        int fid = tid + i * 256;
        int c = fid >> 5, v = (fid & 31) << 2;
        *(float4*)&As[c * 128 + v] = *(const float4*)&xb[(size_t)c * NN + n0 + v];
        *(float4*)&Bs[c * 128 + v] = *(const float4*)&xb[(size_t)c * NN + m0 + v];
    }
    if (tid < 128)       sqn[tid]       = g_sq[b * NN + n0 + tid];
    else                 sqm[tid - 128] = g_sq[b * NN + m0 + (tid - 128)];
    __syncthreads();

    int tx = tid & 15, ty = tid >> 4;

    unsigned long long acc2[8][4];
    #pragma unroll
    for (int i = 0; i < 8; ++i)
        #pragma unroll
        for (int jp = 0; jp < 4; ++jp) acc2[i][jp] = 0ull;

    #pragma unroll 4
    for (int c = 0; c < CC; ++c) {
        float ar[8];
        *(float4*)&ar[0] = *(float4*)&As[c * 128 + ty * 8];
        *(float4*)&ar[4] = *(float4*)&As[c * 128 + ty * 8 + 4];
        ulonglong2 bl = *(ulonglong2*)&Bs[c * 128 + tx * 8];
        ulonglong2 bh = *(ulonglong2*)&Bs[c * 128 + tx * 8 + 4];
        unsigned long long br2[4] = {bl.x, bl.y, bh.x, bh.y};
        #pragma unroll
        for (int i = 0; i < 8; ++i) {
            unsigned long long ad = dup2(ar[i]);
            #pragma unroll
            for (int jp = 0; jp < 4; ++jp)
                ffma2(acc2[i][jp], ad, br2[jp]);
        }
    }

    float acc[8][8];
    #pragma unroll
    for (int i = 0; i < 8; ++i)
        #pragma unroll
        for (int jp = 0; jp < 4; ++jp) {
            float2 f = *(float2*)&acc2[i][jp];
            acc[i][jp * 2]     = f.x;
            acc[i][jp * 2 + 1] = f.y;
        }

    // ---- normal store + n-side chunkmax (coalesced)
    float* outp = g_pd + ((size_t)(b * NN + n0)) * NN + m0;
    float* cmn  = g_cmax + ((size_t)(b * NN + n0)) * 128 + (m0 >> 5);
    #pragma unroll
    for (int i = 0; i < 8; ++i) {
        int r = ty * 8 + i;
        float sn = sqn[r];
        float res[8];
        #pragma unroll
        for (int j = 0; j < 8; ++j)
            res[j] = 2.f * acc[i][j] - sn - sqm[tx * 8 + j];
        *(float4*)&outp[(size_t)r * NN + tx * 8]     = *(float4*)&res[0];
        *(float4*)&outp[(size_t)r * NN + tx * 8 + 4] = *(float4*)&res[4];
        float rm = fmaxf(fmaxf(fmaxf(res[0], res[1]), fmaxf(res[2], res[3])),
                         fmaxf(fmaxf(res[4], res[5]), fmaxf(res[6], res[7])));
        rm = fmaxf(rm, __shfl_xor_sync(FULLMASK, rm, 1));
        rm = fmaxf(rm, __shfl_xor_sync(FULLMASK, rm, 2));
        if ((tx & 3) == 0)
            cmn[(size_t)r * 128 + (tx >> 2)] = rm;
    }

    // ---- mirror via swizzled smem stage, coalesced copy-out + chunkmax
    if (nt != mt) {
        __syncthreads();
        float* stage = (float*)smem_all;
        #pragma unroll
        for (int j = 0; j < 8; ++j) {
            int rm = tx * 8 + j;
            float smv = sqm[rm];
            float tmp[8];
            #pragma unroll
            for (int i = 0; i < 8; ++i)
                tmp[i] = 2.f * acc[i][j] - sqn[ty * 8 + i] - smv;
            int sw = (tx & 15) << 1;
            int s0 = (ty * 2)     ^ sw;
            int s1 = (ty * 2 + 1) ^ sw;
            *(float4*)&stage[rm * 132 + s0 * 4] = *(float4*)&tmp[0];
            *(float4*)&stage[rm * 132 + s1 * 4] = *(float4*)&tmp[4];
        }
        __syncthreads();
        int wid2 = tid >> 5, lane = tid & 31;
        #pragma unroll 4
        for (int it = 0; it < 16; ++it) {
            int mr = it * 8 + wid2;
            int ps = lane ^ (((mr >> 3) & 15) << 1);
            float4 f = *(float4*)&stage[mr * 132 + ps * 4];
            float mx = fmaxf(fmaxf(f.x, f.y), fmaxf(f.z, f.w));
            mx = fmaxf(mx, __shfl_xor_sync(FULLMASK, mx, 1));
            mx = fmaxf(mx, __shfl_xor_sync(FULLMASK, mx, 2));
            mx = fmaxf(mx, __shfl_xor_sync(FULLMASK, mx, 4));
            *(float4*)&g_pd[((size_t)(b * NN + m0 + mr)) * NN + n0 + lane * 4] = f;
            if ((lane & 7) == 0)
                g_cmax[(size_t)(b * NN + m0 + mr) * 128 + nt * 4 + (lane >> 3)] = mx;
        }
    }
}

// float -> descending-orderable key (ascending uint sort picks largest first)
__device__ __forceinline__ unsigned int fdesc_key(float v) {
    unsigned int u = __float_as_uint(v);
    u = u ^ (((int)u >> 31) | 0x80000000u);
    return ~u;
}

// ---------------------------------------------------------------------------
// Kernel 4: warp-per-row top-20 via collect-then-sort with register-batched
// loads: chunk list built from cm regs (no loads), then collect loop unrolled
// x8 -> 8 independent LDGs per serialized round (MLP 8) with tiny smem.
// Fallback to proven sequential scan on cnt>64.
// ---------------------------------------------------------------------------
__global__ __launch_bounds__(256) void topk_fused(
    const float* __restrict__ gamma, const float* __restrict__ beta,
    const float* __restrict__ rmean, const float* __restrict__ rvar,
    float* __restrict__ out)
{
    __shared__ unsigned long long keybuf[8][64];
    __shared__ unsigned char clist[8][128];
    int warp = threadIdx.x >> 5, lane = threadIdx.x & 31;
    int row = blockIdx.x * 8 + warp;        // 0..32767
    int b = row >> 12, n = row & 4095;

    const float* cmrow = g_cmax + (size_t)row * 128;
    float cm[4];
    #pragma unroll
    for (int j = 0; j < 4; ++j) cm[j] = __ldg(&cmrow[j * 32 + lane]);
    float lmax = fmaxf(fmaxf(cm[0], cm[1]), fmaxf(cm[2], cm[3]));

    // bitonic sort 32 lane-group maxes ascending across lanes
    float s = lmax;
    #pragma unroll
    for (int k2 = 2; k2 <= 32; k2 <<= 1) {
        #pragma unroll
        for (int j2 = k2 >> 1; j2 > 0; j2 >>= 1) {
            float o = __shfl_xor_sync(FULLMASK, s, j2);
            bool dirAsc = ((lane & k2) == 0);
            bool upper  = ((lane & j2) == 0);
            float mn = fminf(s, o), mx = fmaxf(s, o);
            s = (dirAsc == upper) ? mn : mx;
        }
    }
    float T0 = __shfl_sync(FULLMASK, s, 32 - KNB);   // 20th largest group max

    const float* rowf = g_pd + (size_t)row * NN;
    unsigned lanelt = (1u << lane) - 1u;

    // ---- build candidate chunk list (register-only ballots, no loads)
    int nc = 0;
    #pragma unroll
    for (int j = 0; j < 4; ++j) {
        unsigned m = __ballot_sync(FULLMASK, cm[j] >= T0);
        if (cm[j] >= T0) {
            int pos = nc + __popc(m & lanelt);
            if (pos < 128) clist[warp][pos] = (unsigned char)(j * 32 + lane);
        }
        nc += __popc(m);
    }
    __syncwarp();
    if (nc > 128) nc = 128;

    // ---- collect: batches of 8 independent loads, then 8 ballots/compacts
    int cnt = 0;
    for (int i0 = 0; i0 < nc; i0 += 8) {
        float vv[8];
        int   ch[8];
        #pragma unroll
        for (int j = 0; j < 8; ++j) {
            int i = i0 + j;
            if (i < nc) {
                ch[j] = clist[warp][i];
                vv[j] = __ldg(&rowf[ch[j] * 32 + lane]);
            } else {
                ch[j] = 0;
                vv[j] = -FLT_MAX;
            }
        }
        #pragma unroll
        for (int j = 0; j < 8; ++j) {
            unsigned m = __ballot_sync(FULLMASK, vv[j] >= T0);
            int pos = cnt + __popc(m & lanelt);
            if (vv[j] >= T0 && pos < 64) {
                unsigned long long key =
                    ((unsigned long long)fdesc_key(vv[j]) << 32)
                    | (unsigned int)(ch[j] * 32 + lane);
                keybuf[warp][pos] = key;
            }
            cnt += __popc(m);
        }
    }

    int li = 0;   // lanes 0..19 will hold the top-20 indices
    if (cnt <= 64) {
        // ---- 64-element bitonic sort (2 keys/lane)
        const unsigned long long PADK = 0xFFFFFFFFFFFFFFFFull;
        unsigned long long e0 = (lane      < cnt) ? keybuf[warp][lane]      : PADK;
        unsigned long long e1 = (lane + 32 < cnt) ? keybuf[warp][lane + 32] : PADK;
        #pragma unroll
        for (int k2 = 2; k2 <= 64; k2 <<= 1) {
            #pragma unroll
            for (int j2 = k2 >> 1; j2 > 0; j2 >>= 1) {
                if (j2 == 32) {
                    unsigned long long lo = e0 < e1 ? e0 : e1;
                    unsigned long long hi = e0 < e1 ? e1 : e0;
                    e0 = lo; e1 = hi;
                } else {
                    bool up = ((lane & j2) == 0);
                    {
                        bool asc = ((lane & k2) == 0) || (k2 == 64);
                        unsigned long long o = __shfl_xor_sync(FULLMASK, e0, j2);
                        unsigned long long mn = e0 < o ? e0 : o;
                        unsigned long long mx = e0 < o ? o : e0;
                        e0 = (asc == up) ? mn : mx;
                    }
                    {
                        bool asc = (((lane + 32) & k2) == 0) || (k2 == 64);
                        unsigned long long o = __shfl_xor_sync(FULLMASK, e1, j2);
                        unsigned long long mn = e1 < o ? e1 : o;
                        unsigned long long mx = e1 < o ? o : e1;
                        e1 = (asc == up) ? mn : mx;
                    }
                }
            }
        }
        li = (int)(unsigned int)(e0 & 0xFFFFFFFFull);
    } else {
        // ---- rare overflow: exact sequential insert scan (proven path)
        float lv = -FLT_MAX;
        float vmin = -FLT_MAX;
        int   minpos = 0;
        #pragma unroll
        for (int j = 0; j < 4; ++j) {
            unsigned cmask = __ballot_sync(FULLMASK, cm[j] >= T0);
            while (cmask) {
                int q = __ffs(cmask) - 1;
                cmask &= cmask - 1;
                float cmv = __shfl_sync(FULLMASK, cm[j], q);
                if (cmv <= vmin && vmin > -FLT_MAX) continue;
                int chunk = j * 32 + q;
                float v = __ldg(&rowf[chunk * 32 + lane]);
                unsigned m = __ballot_sync(FULLMASK, v >= T0 && v > vmin);
                while (m) {
                    int lead = __ffs(m) - 1;
                    float cv = __shfl_sync(FULLMASK, v, lead);
                    int   ci = chunk * 32 + lead;
                    if (lane == minpos) { lv = cv; li = ci; }
                    float tt = (lane < KNB) ? lv : FLT_MAX;
                    #pragma unroll
                    for (int off = 16; off; off >>= 1)
                        tt = fminf(tt, __shfl_xor_sync(FULLMASK, tt, off));
                    vmin = tt;
                    minpos = __ffs(__ballot_sync(FULLMASK,
                                                 lane < KNB && lv == vmin)) - 1;
                    m &= ~(1u << lead);
                    m &= __ballot_sync(FULLMASK, v > vmin);
                }
            }
        }
    }

    // ---- fused epilogue: out[b,o,n] = max_k leaky(BN(P[row,o] + Q[idx_k,o]))
    float sc1 = gamma[lane]      * rsqrtf(rvar[lane]      + 1e-5f);
    float sc2 = gamma[lane + 32] * rsqrtf(rvar[lane + 32] + 1e-5f);
    float bi1 = beta[lane]      - rmean[lane]      * sc1;
    float bi2 = beta[lane + 32] - rmean[lane + 32] * sc2;
    float p1 = g_P[(size_t)row * OO + lane];
    float p2 = g_P[(size_t)row * OO + lane + 32];
    const float* Qb = g_Q + (size_t)b * NN * OO;

    float m1 = -FLT_MAX, m2 = -FLT_MAX;
    #pragma unroll
    for (int kk = 0; kk < KNB; ++kk) {
        int nid = __shfl_sync(FULLMASK, li, kk);
        const float* Qr = Qb + (size_t)nid * OO;
        float y1 = (p1 + __ldg(&Qr[lane]))      * sc1 + bi1;
        float y2 = (p2 + __ldg(&Qr[lane + 32])) * sc2 + bi2;
        y1 = (y1 >= 0.f) ? y1 : 0.2f * y1;
        y2 = (y2 >= 0.f) ? y2 : 0.2f * y2;
        m1 = fmaxf(m1, y1);
        m2 = fmaxf(m2, y2);
    }
    out[((size_t)b * OO + lane)      * NN + n] = m1;
    out[((size_t)b * OO + lane + 32) * NN + n] = m2;
}

// ---------------------------------------------------------------------------
extern "C" void kernel_launch(void* const* d_in, const int* in_sizes, int n_in,
                              void* d_out, int out_size) {
    const float* x     = (const float*)d_in[0];
    const float* W     = (const float*)d_in[1];
    const float* gamma = (const float*)d_in[2];
    const float* beta  = (const float*)d_in[3];
    const float* rmean = (const float*)d_in[4];
    const float* rvar  = (const float*)d_in[5];
    float* out = (float*)d_out;

    sq_kernel<<<128, 256>>>(x);
    pq_kernel<<<8192, 256>>>(x, W);
    {
        dim3 grid(528, 1, BB);
        pd_gemm_sym<<<grid, 256>>>(x);
    }
    topk_fused<<<4096, 256>>>(gamma, beta, rmean, rvar, out);
}